// round 4
// baseline (speedup 1.0000x reference)
#include <cuda_runtime.h>
#include <cstddef>

#define NPTS 1024
#define DIM  128
#define FULLMASK 0xffffffffu
#define CAP 256

__device__ __forceinline__ float warp_sum(float v) {
#pragma unroll
    for (int o = 16; o > 0; o >>= 1) v += __shfl_xor_sync(FULLMASK, v, o);
    return v;
}

// atanh(min(s,1-1e-7)) via fast log; s >= 0
__device__ __forceinline__ float fast_atanh(float s) {
    s = fminf(s, 1.0f - 1e-7f);
    return 0.5f * __logf(__fdividef(1.0f + s, 1.0f - s));
}

// ---------------------------------------------------------------------------
// One fused kernel: block (128 threads, 4 warps) per row i.
//  step0: row stats (x2_i, left_i) ; stage x_i, w_right in smem
//  step1: ballot-compact nonzero adj entries (4 warps x 256 entries)
//  step2: quad-per-pair dots (4 lanes x 32-dim slice each -> 8 wavefronts
//         per warp LDG instead of 32) + 2-shuffle quad reduce + scalar chain
//  step3: dim-per-lane coalesced aggregation u = sum wb_j x_j (4 warps)
//  step4: expmap epilogue on warp 0
// ---------------------------------------------------------------------------
__global__ void __launch_bounds__(128) k_fused(
    const float* __restrict__ x, const float* __restrict__ adj,
    const float* __restrict__ attw, const float* __restrict__ attb,
    float* __restrict__ out)
{
    __shared__ __align__(16) float s_xi[DIM];
    __shared__ __align__(16) float s_w2[DIM];
    __shared__ int   s_idx[CAP];
    __shared__ float s_val[CAP];
    __shared__ float s_wb[CAP];
    __shared__ __align__(16) float s_u[4][DIM];
    __shared__ float s_red[12];
    __shared__ int   s_wcnt[4];

    const int i    = blockIdx.x;
    const int t    = threadIdx.x;          // 0..127
    const int warp = t >> 5, lane = t & 31;

    // ---- step 0: stage x_i, w2; row stats ----
    float a = x[i * DIM + t];
    s_xi[t] = a;
    s_w2[t] = attw[DIM + t];
    float x2p = a * a;
    float d1p = a * attw[t];
    x2p = warp_sum(x2p); d1p = warp_sum(d1p);
    if (lane == 0) { s_red[warp] = x2p; s_red[4 + warp] = d1p; }
    __syncthreads();
    const float x2i = s_red[0] + s_red[1] + s_red[2] + s_red[3];
    const float d1  = s_red[4] + s_red[5] + s_red[6] + s_red[7];
    const float pni = sqrtf(fmaxf(x2i, 1e-15f));
    const float lt  = fast_atanh(pni) / pni * d1 + attb[0];
    const float omi  = 1.0f - x2i;
    const float omci = fmaxf(omi, 1e-15f);

    // ---- step 1: compaction (warp w scans 256 entries) ----
    const float* arow = adj + (size_t)i * NPTS + warp * 256;
    unsigned masks[8]; float vals[8];
    int mycnt = 0;
#pragma unroll
    for (int c = 0; c < 8; c++) {
        float v = arow[c * 32 + lane];
        vals[c] = v;
        unsigned m = __ballot_sync(FULLMASK, v != 0.0f);
        masks[c] = m;
        mycnt += __popc(m);
    }
    if (lane == 0) s_wcnt[warp] = mycnt;
    __syncthreads();
    int run = 0;
#pragma unroll
    for (int w = 0; w < 4; w++) if (w < warp) run += s_wcnt[w];
#pragma unroll
    for (int c = 0; c < 8; c++) {
        unsigned m = masks[c];
        if (m & (1u << lane)) {
            int pos = run + __popc(m & ((1u << lane) - 1));
            if (pos < CAP) { s_idx[pos] = warp * 256 + c * 32 + lane; s_val[pos] = vals[c]; }
        }
        run += __popc(m);
    }
    const int cnt = min(s_wcnt[0] + s_wcnt[1] + s_wcnt[2] + s_wcnt[3], CAP);
    __syncthreads();

    // ---- step 2: quad-per-pair scalar chain (32 pairs per sweep) ----
    const int slice = lane & 3;            // 32-dim slice within the pair
    float4 xir[8];
#pragma unroll
    for (int m = 0; m < 8; m++) xir[m] = ((const float4*)s_xi)[slice * 8 + m];

    float wa_lane = 0.0f;
    for (int kb = 0; kb < cnt; kb += 32) {
        int  k   = kb + warp * 8 + (lane >> 2);
        bool act = k < cnt;
        int  j   = act ? s_idx[k] : i;
        float av = act ? s_val[k] : 0.0f;
        const float4* xj4 = (const float4*)(x + j * DIM) + slice * 8;
        float d = 0.f, x2j = 0.f, d2j = 0.f;
#pragma unroll
        for (int m = 0; m < 8; m++) {
            float4 b  = xj4[m];
            float4 aa = xir[m];
            float4 w  = ((const float4*)s_w2)[slice * 8 + m];
            d   += aa.x * b.x + aa.y * b.y + aa.z * b.z + aa.w * b.w;
            x2j += b.x * b.x + b.y * b.y + b.z * b.z + b.w * b.w;
            d2j += w.x * b.x + w.y * b.y + w.z * b.z + w.w * b.w;
        }
        d   += __shfl_xor_sync(FULLMASK, d, 1);   d   += __shfl_xor_sync(FULLMASK, d, 2);
        x2j += __shfl_xor_sync(FULLMASK, x2j, 1); x2j += __shfl_xor_sync(FULLMASK, x2j, 2);
        d2j += __shfl_xor_sync(FULLMASK, d2j, 1); d2j += __shfl_xor_sync(FULLMASK, d2j, 2);

        // attention (sigmoid with recomputed right_j); av=0 kills inactive lanes
        float pnj  = sqrtf(fmaxf(x2j, 1e-15f));
        float rtj  = fast_atanh(pnj) / pnj * d2j;
        float sig  = __fdividef(av, 1.0f + __expf(-(lt + rtj)));
        // pairwise logmap scalar chain
        float P   = 1.0f - 2.0f * d;
        float A   = P + x2j;                             // coeff of -x_i
        float den = fmaxf(P + x2i * x2j, 1e-15f);        // mobius denom
        float Q   = x2i * A * A - 2.0f * A * omi * d + x2j * omi * omi;
        Q = fmaxf(Q, 1e-15f * den * den);                // sn2 clamp * den^2
        float rq  = rsqrtf(Q);
        float sq  = Q * rq;                              // sqrt(Q)
        float dm  = fmaxf(den - sq, 1e-7f * den);        // atanh clip
        float ath = 0.5f * __logf(__fdividef(den + sq, dm));
        float wgt = sig * omci * ath * rq;
        if (slice == 0) {
            wa_lane += wgt * A;
            if (act) s_wb[k] = wgt * omi;
        }
    }
    wa_lane = warp_sum(wa_lane);
    if (lane == 0) s_red[8 + warp] = wa_lane;
    __syncthreads();

    // ---- step 3: dim-per-lane coalesced aggregation ----
    float4 u = {0.f, 0.f, 0.f, 0.f};
    for (int k = warp; k < cnt; k += 4) {
        float wb = s_wb[k];
        float4 b = *(const float4*)(x + s_idx[k] * DIM + 4 * lane);
        u.x += wb * b.x; u.y += wb * b.y; u.z += wb * b.z; u.w += wb * b.w;
    }
    ((float4*)s_u[warp])[lane] = u;
    __syncthreads();

    // ---- step 4: expmap epilogue (warp 0, float4 per lane covers D=128) ----
    if (warp == 0) {
        float4 u0 = ((const float4*)s_u[0])[lane];
        float4 u1 = ((const float4*)s_u[1])[lane];
        float4 u2 = ((const float4*)s_u[2])[lane];
        float4 u3 = ((const float4*)s_u[3])[lane];
        float  wa = s_red[8] + s_red[9] + s_red[10] + s_red[11];
        float4 xi = ((const float4*)s_xi)[lane];
        float4 uu;
        uu.x = (u0.x + u1.x) + (u2.x + u3.x) - wa * xi.x;
        uu.y = (u0.y + u1.y) + (u2.y + u3.y) - wa * xi.y;
        uu.z = (u0.z + u1.z) + (u2.z + u3.z) - wa * xi.z;
        uu.w = (u0.w + u1.w) + (u2.w + u3.w) - wa * xi.w;
        float su2 = uu.x * uu.x + uu.y * uu.y + uu.z * uu.z + uu.w * uu.w;
        float sxu = xi.x * uu.x + xi.y * uu.y + xi.z * uu.z + xi.w * uu.w;
#pragma unroll
        for (int o = 16; o > 0; o >>= 1) {
            su2 += __shfl_xor_sync(FULLMASK, su2, o);
            sxu += __shfl_xor_sync(FULLMASK, sxu, o);
        }
        float un   = sqrtf(fmaxf(su2, 1e-15f));
        float coef = tanhf(un / omci) / un;     // tanh(lam*un/2)/un
        float xy   = coef * sxu;
        float y2   = coef * coef * su2;
        float den  = fmaxf(1.0f + 2.0f * xy + x2i * y2, 1e-15f);
        float An   = 1.0f + 2.0f * xy + y2;
        float Bn   = omi * coef;
        float inv  = 1.0f / den;
        float4 o;
        o.x = (An * xi.x + Bn * uu.x) * inv;
        o.y = (An * xi.y + Bn * uu.y) * inv;
        o.z = (An * xi.z + Bn * uu.z) * inv;
        o.w = (An * xi.w + Bn * uu.w) * inv;
        *(float4*)&out[i * DIM + 4 * lane] = o;
    }
}

// ---------------------------------------------------------------------------
extern "C" void kernel_launch(void* const* d_in, const int* in_sizes, int n_in,
                              void* d_out, int out_size) {
    const float* x    = (const float*)d_in[0];   // [1,1024,128]
    const float* adj  = (const float*)d_in[1];   // [1,1024,1024]
    const float* attw = (const float*)d_in[2];   // [256]
    const float* attb = (const float*)d_in[3];   // scalar
    float* out = (float*)d_out;                  // [1,1024,128]

    k_fused<<<NPTS, 128>>>(x, adj, attw, attb, out);
}

// round 5
// speedup vs baseline: 1.3538x; 1.3538x over previous
#include <cuda_runtime.h>
#include <cstddef>

#define NPTS 1024
#define DIM  128
#define FULLMASK 0xffffffffu
#define CAP 256

__device__ __forceinline__ float warp_sum(float v) {
#pragma unroll
    for (int o = 16; o > 0; o >>= 1) v += __shfl_xor_sync(FULLMASK, v, o);
    return v;
}

// atanh(min(s,1-1e-7)) via fast log; s >= 0
__device__ __forceinline__ float fast_atanh(float s) {
    s = fminf(s, 1.0f - 1e-7f);
    return 0.5f * __logf(__fdividef(1.0f + s, 1.0f - s));
}

// ---------------------------------------------------------------------------
// One fused kernel: block (128 threads, 4 warps) per row i.
//  step2 uses INTERLEAVED quad slicing: lane (slice s of a quad) owns float4
//  indices {m*4+s}, so each quad covers a contiguous 64B span per m and one
//  warp LDG.128 touches 8 rows x 64B = 8 wavefronts (not 32).
// ---------------------------------------------------------------------------
__global__ void __launch_bounds__(128, 6) k_fused(
    const float* __restrict__ x, const float* __restrict__ adj,
    const float* __restrict__ attw, const float* __restrict__ attb,
    float* __restrict__ out)
{
    __shared__ __align__(16) float s_xi[DIM];
    __shared__ __align__(16) float s_w2[DIM];
    __shared__ int   s_idx[CAP];
    __shared__ float s_val[CAP];
    __shared__ float s_wb[CAP];
    __shared__ __align__(16) float s_u[4][DIM];
    __shared__ float s_red[12];
    __shared__ int   s_wcnt[4];

    const int i    = blockIdx.x;
    const int t    = threadIdx.x;          // 0..127
    const int warp = t >> 5, lane = t & 31;

    // ---- step 0: stage x_i, w2; row stats ----
    float a = x[i * DIM + t];
    s_xi[t] = a;
    s_w2[t] = attw[DIM + t];
    float x2p = a * a;
    float d1p = a * attw[t];
    x2p = warp_sum(x2p); d1p = warp_sum(d1p);
    if (lane == 0) { s_red[warp] = x2p; s_red[4 + warp] = d1p; }
    __syncthreads();
    const float x2i = s_red[0] + s_red[1] + s_red[2] + s_red[3];
    const float d1  = s_red[4] + s_red[5] + s_red[6] + s_red[7];
    const float pni = sqrtf(fmaxf(x2i, 1e-15f));
    const float lt  = fast_atanh(pni) / pni * d1 + attb[0];
    const float omi  = 1.0f - x2i;
    const float omci = fmaxf(omi, 1e-15f);

    // ---- step 1: compaction (warp w scans 256 entries; vals re-read) ----
    const float* arow = adj + (size_t)i * NPTS + warp * 256;
    unsigned masks[8];
    int mycnt = 0;
#pragma unroll
    for (int c = 0; c < 8; c++) {
        float v = arow[c * 32 + lane];
        unsigned m = __ballot_sync(FULLMASK, v != 0.0f);
        masks[c] = m;
        mycnt += __popc(m);
    }
    if (lane == 0) s_wcnt[warp] = mycnt;
    __syncthreads();
    int run = 0;
#pragma unroll
    for (int w = 0; w < 4; w++) if (w < warp) run += s_wcnt[w];
#pragma unroll
    for (int c = 0; c < 8; c++) {
        unsigned m = masks[c];
        if (m & (1u << lane)) {
            int pos = run + __popc(m & ((1u << lane) - 1));
            if (pos < CAP) {
                s_idx[pos] = warp * 256 + c * 32 + lane;
                s_val[pos] = arow[c * 32 + lane];   // L1 hit
            }
        }
        run += __popc(m);
    }
    const int cnt = min(s_wcnt[0] + s_wcnt[1] + s_wcnt[2] + s_wcnt[3], CAP);
    __syncthreads();

    // ---- step 2: quad-per-pair, interleaved slices (32 pairs per sweep) ----
    const int slice = lane & 3;
    float4 xir[8];
#pragma unroll
    for (int m = 0; m < 8; m++) xir[m] = ((const float4*)s_xi)[m * 4 + slice];

    float wa_lane = 0.0f;
    for (int kb = 0; kb < cnt; kb += 32) {
        int  k   = kb + warp * 8 + (lane >> 2);
        bool act = k < cnt;
        int  j   = act ? s_idx[k] : i;
        float av = act ? s_val[k] : 0.0f;
        const float4* xj4 = (const float4*)(x + j * DIM);
        float d = 0.f, x2j = 0.f, d2j = 0.f;
#pragma unroll
        for (int m = 0; m < 8; m++) {
            float4 b  = xj4[m * 4 + slice];            // quad covers 64B/m
            float4 aa = xir[m];
            float4 w  = ((const float4*)s_w2)[m * 4 + slice];
            d   += aa.x * b.x + aa.y * b.y + aa.z * b.z + aa.w * b.w;
            x2j += b.x * b.x + b.y * b.y + b.z * b.z + b.w * b.w;
            d2j += w.x * b.x + w.y * b.y + w.z * b.z + w.w * b.w;
        }
        d   += __shfl_xor_sync(FULLMASK, d, 1);   d   += __shfl_xor_sync(FULLMASK, d, 2);
        x2j += __shfl_xor_sync(FULLMASK, x2j, 1); x2j += __shfl_xor_sync(FULLMASK, x2j, 2);
        d2j += __shfl_xor_sync(FULLMASK, d2j, 1); d2j += __shfl_xor_sync(FULLMASK, d2j, 2);

        // attention (sigmoid with recomputed right_j); av=0 kills inactive lanes
        float pnj  = sqrtf(fmaxf(x2j, 1e-15f));
        float rtj  = fast_atanh(pnj) / pnj * d2j;
        float sig  = __fdividef(av, 1.0f + __expf(-(lt + rtj)));
        // pairwise logmap scalar chain
        float P   = 1.0f - 2.0f * d;
        float A   = P + x2j;                             // coeff of -x_i
        float den = fmaxf(P + x2i * x2j, 1e-15f);        // mobius denom
        float Q   = x2i * A * A - 2.0f * A * omi * d + x2j * omi * omi;
        Q = fmaxf(Q, 1e-15f * den * den);                // sn2 clamp * den^2
        float rq  = rsqrtf(Q);
        float sq  = Q * rq;                              // sqrt(Q)
        float dm  = fmaxf(den - sq, 1e-7f * den);        // atanh clip
        float ath = 0.5f * __logf(__fdividef(den + sq, dm));
        float wgt = sig * omci * ath * rq;
        if (slice == 0) {
            wa_lane += wgt * A;
            if (act) s_wb[k] = wgt * omi;
        }
    }
    wa_lane = warp_sum(wa_lane);
    if (lane == 0) s_red[8 + warp] = wa_lane;
    __syncthreads();

    // ---- step 3: dim-per-lane coalesced aggregation ----
    float4 u = {0.f, 0.f, 0.f, 0.f};
    for (int k = warp; k < cnt; k += 4) {
        float wb = s_wb[k];
        float4 b = *(const float4*)(x + s_idx[k] * DIM + 4 * lane);
        u.x += wb * b.x; u.y += wb * b.y; u.z += wb * b.z; u.w += wb * b.w;
    }
    ((float4*)s_u[warp])[lane] = u;
    __syncthreads();

    // ---- step 4: expmap epilogue (warp 0, float4 per lane covers D=128) ----
    if (warp == 0) {
        float4 u0 = ((const float4*)s_u[0])[lane];
        float4 u1 = ((const float4*)s_u[1])[lane];
        float4 u2 = ((const float4*)s_u[2])[lane];
        float4 u3 = ((const float4*)s_u[3])[lane];
        float  wa = s_red[8] + s_red[9] + s_red[10] + s_red[11];
        float4 xi = ((const float4*)s_xi)[lane];
        float4 uu;
        uu.x = (u0.x + u1.x) + (u2.x + u3.x) - wa * xi.x;
        uu.y = (u0.y + u1.y) + (u2.y + u3.y) - wa * xi.y;
        uu.z = (u0.z + u1.z) + (u2.z + u3.z) - wa * xi.z;
        uu.w = (u0.w + u1.w) + (u2.w + u3.w) - wa * xi.w;
        float su2 = uu.x * uu.x + uu.y * uu.y + uu.z * uu.z + uu.w * uu.w;
        float sxu = xi.x * uu.x + xi.y * uu.y + xi.z * uu.z + xi.w * uu.w;
#pragma unroll
        for (int o = 16; o > 0; o >>= 1) {
            su2 += __shfl_xor_sync(FULLMASK, su2, o);
            sxu += __shfl_xor_sync(FULLMASK, sxu, o);
        }
        float un   = sqrtf(fmaxf(su2, 1e-15f));
        float coef = tanhf(un / omci) / un;     // tanh(lam*un/2)/un
        float xy   = coef * sxu;
        float y2   = coef * coef * su2;
        float den  = fmaxf(1.0f + 2.0f * xy + x2i * y2, 1e-15f);
        float An   = 1.0f + 2.0f * xy + y2;
        float Bn   = omi * coef;
        float inv  = 1.0f / den;
        float4 o;
        o.x = (An * xi.x + Bn * uu.x) * inv;
        o.y = (An * xi.y + Bn * uu.y) * inv;
        o.z = (An * xi.z + Bn * uu.z) * inv;
        o.w = (An * xi.w + Bn * uu.w) * inv;
        *(float4*)&out[i * DIM + 4 * lane] = o;
    }
}

// ---------------------------------------------------------------------------
extern "C" void kernel_launch(void* const* d_in, const int* in_sizes, int n_in,
                              void* d_out, int out_size) {
    const float* x    = (const float*)d_in[0];   // [1,1024,128]
    const float* adj  = (const float*)d_in[1];   // [1,1024,1024]
    const float* attw = (const float*)d_in[2];   // [256]
    const float* attb = (const float*)d_in[3];   // scalar
    float* out = (float*)d_out;                  // [1,1024,128]

    k_fused<<<NPTS, 128>>>(x, adj, attw, attb, out);
}